// round 15
// baseline (speedup 1.0000x reference)
#include <cuda_runtime.h>
#include <cuda_fp16.h>
#include <math.h>
#include <stdint.h>

#define BATCH 64
#define TSTEPS 60
#define MAXFRAME 40
#define CAPLEN 20
#define HDIM 512
#define XDIM 1024
#define GDIM 2048
#define VOCAB 32000
#define OUTROWS 1216
#define GH 520
#define ENCROWS (MAXFRAME * BATCH)           // 2560
#define DECROWS (CAPLEN * BATCH)             // 1280
#define TSPLIT 50

// ---------------- device scratch ----------------
__device__ __half g_XencH[ENCROWS * HDIM];
__device__ __half g_XdecH[DECROWS * XDIM];
__device__ float  g_G[TSTEPS * BATCH * GDIM];
__device__ float  g_bias[GDIM];
__device__ __half g_WihH[GDIM * XDIM];
__device__ __half g_WlinH[VOCAB * HDIM];
__device__ __half g_hH[2][BATCH * GH];
__device__ __half g_dechT[1280 * HDIM];      // t-major: row = t'*64 + b
__device__ float  g_cstate[BATCH * HDIM];
__device__ unsigned g_cnt[TSTEPS];

// ---------------- helpers ----------------
__device__ __forceinline__ uint32_t f2h2(float a, float b) {
    __half2 h = __floats2half2_rn(a, b);
    return *(uint32_t*)&h;
}
__device__ __forceinline__ void mma_h16(float* c, const uint32_t* a, const uint32_t* b) {
    asm volatile(
        "mma.sync.aligned.m16n8k16.row.col.f32.f16.f16.f32 "
        "{%0,%1,%2,%3}, {%4,%5,%6,%7}, {%8,%9}, {%0,%1,%2,%3};"
        : "+f"(c[0]), "+f"(c[1]), "+f"(c[2]), "+f"(c[3])
        : "r"(a[0]), "r"(a[1]), "r"(a[2]), "r"(a[3]), "r"(b[0]), "r"(b[1]));
}
__device__ __forceinline__ float sigf(float x) { return 1.f / (1.f + __expf(-x)); }
__device__ __forceinline__ void cp16(uint32_t d, const void* s) {
    asm volatile("cp.async.cg.shared.global [%0], [%1], 16;" :: "r"(d), "l"(s));
}
#define CP_COMMIT() asm volatile("cp.async.commit_group;" ::: "memory")
#define CP_WAIT1()  asm volatile("cp.async.wait_group 1;" ::: "memory")
#define CP_WAIT0()  asm volatile("cp.async.wait_group 0;" ::: "memory")
#define LDSM4(r0, r1, r2, r3, a) \
    asm volatile("ldmatrix.sync.aligned.m8n8.x4.shared.b16 {%0,%1,%2,%3}, [%4];" \
        : "=r"(r0), "=r"(r1), "=r"(r2), "=r"(r3) : "r"(a))
#define MBAR_INIT(mb, c) asm volatile("mbarrier.init.shared.b64 [%0], %1;" :: "r"(mb), "r"(c) : "memory")
__device__ __forceinline__ void mbar_wait(uint32_t mb, uint32_t parity) {
    asm volatile(
        "{\n\t.reg .pred P;\n\t"
        "LAB_W%=:\n\t"
        "mbarrier.try_wait.parity.acquire.cta.shared::cta.b64 P, [%0], %1, 0x989680;\n\t"
        "@P bra.uni LAB_D%=;\n\t"
        "bra.uni LAB_W%=;\n\t"
        "LAB_D%=:\n\t}" :: "r"(mb), "r"(parity) : "memory");
}
__device__ __forceinline__ void bulk_ld(uint32_t dst, const void* src, uint32_t bytes, uint32_t mb) {
    asm volatile(
        "cp.async.bulk.shared::cluster.global.mbarrier::complete_tx::bytes [%0], [%1], %2, [%3];"
        :: "r"(dst), "l"(src), "r"(bytes), "r"(mb) : "memory");
}

// ---------------- build enc A ----------------
__global__ void build_encA(const float* __restrict__ feature) {
    int idx = blockIdx.x * 256 + threadIdx.x;
    int r = idx >> 6, c8 = idx & 63;
    int t = r >> 6, b = r & 63;
    const float4* src = (const float4*)&feature[((size_t)b * TSTEPS + t) * HDIM + c8 * 8];
    float4 lo = src[0], hi = src[1];
    uint4 o;
    o.x = f2h2(lo.x, lo.y); o.y = f2h2(lo.z, lo.w);
    o.z = f2h2(hi.x, hi.y); o.w = f2h2(hi.z, hi.w);
    ((uint4*)g_XencH)[idx] = o;
}

// ---------------- build dec A ----------------
__global__ void build_decA(const float* __restrict__ feature,
                           const int* __restrict__ captions,
                           const float* __restrict__ embedding) {
    int idx = blockIdx.x * 256 + threadIdx.x;
    int r = idx >> 7, c8 = idx & 127;
    int tp = r >> 6, b = r & 63;
    float4 lo, hi;
    if (c8 < 64) {
        int cap = captions[b * CAPLEN + tp];
        const float4* src = (const float4*)&embedding[(size_t)cap * HDIM + c8 * 8];
        lo = src[0]; hi = src[1];
    } else {
        const float4* src = (const float4*)&feature[((size_t)b * TSTEPS + MAXFRAME + tp) * HDIM + (c8 - 64) * 8];
        lo = src[0]; hi = src[1];
    }
    uint4 o;
    o.x = f2h2(lo.x, lo.y); o.y = f2h2(lo.z, lo.w);
    o.z = f2h2(hi.x, hi.y); o.w = f2h2(hi.z, hi.w);
    ((uint4*)g_XdecH)[idx] = o;
}

// ---------------- fp32 -> fp16 convert ----------------
__global__ void conv_h(const float* __restrict__ s, __half* __restrict__ d, int n8) {
    int i = blockIdx.x * 256 + threadIdx.x;
    if (i < n8) {
        float4 a = ((const float4*)s)[i * 2];
        float4 b = ((const float4*)s)[i * 2 + 1];
        uint4 o;
        o.x = f2h2(a.x, a.y); o.y = f2h2(a.z, a.w);
        o.z = f2h2(b.x, b.y); o.w = f2h2(b.z, b.w);
        ((uint4*)d)[i] = o;
    }
}

// ---------------- prep ----------------
__global__ void prep_kernel(const float* __restrict__ b_ih, const float* __restrict__ b_hh) {
    int idx = blockIdx.x * 256 + threadIdx.x;
    ((uint32_t*)g_hH)[idx] = 0u;
    ((uint32_t*)g_hH)[idx + 16384] = 0u;
    if (idx < 512) ((uint32_t*)g_hH)[idx + 32768] = 0u;
    ((uint32_t*)g_dechT)[OUTROWS * HDIM / 2 + idx] = 0u;
    if (idx < GDIM) g_bias[idx] = b_ih[idx] + b_hh[idx];
    if (idx < TSTEPS) g_cnt[idx] = 0u;
}

// ---------------- fp16 mma GEMM: block 128x64, 3 CTAs/SM ----------------
// C[M,N] = A[M,K]*B[N,K]^T + bias[N]. BK=32, 256 thr, warps 4(M)x2(N),
// warp tile 32x32, m16n8k16, cp.async 3-stage, sw-pipelined frags.
#define GP 40
#define STAGE_B ((128 + 64) * GP * 2)        // 15360 B
#define BOFF (128 * GP * 2)                  // B area offset within stage
#define GEMM_SMEM (3 * STAGE_B)              // 46080 B

__device__ __forceinline__ void ld_frags(uint32_t sA, uint32_t sB, int k0,
                                         int arow, int acol, int brow, int bcol,
                                         uint32_t af[2][4], uint32_t bf[4][2]) {
#pragma unroll
    for (int mi = 0; mi < 2; mi++)
        LDSM4(af[mi][0], af[mi][1], af[mi][2], af[mi][3],
              sA + (uint32_t)((arow + mi * 16) * GP + k0 + acol) * 2);
#pragma unroll
    for (int p = 0; p < 2; p++)
        LDSM4(bf[2 * p][0], bf[2 * p][1], bf[2 * p + 1][0], bf[2 * p + 1][1],
              sB + (uint32_t)((brow + p * 16) * GP + k0 + bcol) * 2);
}

__global__ void __launch_bounds__(256, 3)
h16_gemm(const __half* __restrict__ A, int lda,
         const __half* __restrict__ B, int ldb,
         const float* __restrict__ bias, float* __restrict__ C,
         int M, int N, int K, int remap, int rowbase) {
    extern __shared__ __half sh[];
    uint32_t sbase;
    asm("{ .reg .u64 t; cvta.to.shared.u64 t, %1; cvt.u32.u64 %0, t; }" : "=r"(sbase) : "l"(sh));

    const int tid = threadIdx.x, lane = tid & 31, wid = tid >> 5;
    const int wm = wid & 3, wn = wid >> 2;
    const int g = lane >> 2, tig = lane & 3;
    const int bm = blockIdx.y * 128, bn = blockIdx.x * 64;

    // fill mapping: A 512 cp16 (2/thr), B 256 cp16 (1/thr)
    const int farow = tid >> 1, faq = (tid & 1) * 2;         // A: row, quarter*2
    const int fbrow = tid >> 2, fbq = tid & 3;               // B: row, quarter
    const __half* gA = &A[(size_t)(bm + farow) * lda + faq * 8];
    const __half* gB = &B[(size_t)(bn + fbrow) * ldb + fbq * 8];
    const uint32_t faoff = (uint32_t)(farow * GP + faq * 8) * 2;
    const uint32_t fboff = (uint32_t)(BOFF) + (uint32_t)(fbrow * GP + fbq * 8) * 2;

    const int arow = wm * 32 + ((lane & 7) | (((lane >> 3) & 1) << 3));
    const int acol = (lane >> 4) * 8;
    const int brow = wn * 32 + (lane & 7) + ((lane >> 4) << 3);
    const int bcol = ((lane >> 3) & 1) * 8;

    float acc[2][4][4];
#pragma unroll
    for (int mi = 0; mi < 2; mi++)
#pragma unroll
        for (int nj = 0; nj < 4; nj++)
#pragma unroll
            for (int i = 0; i < 4; i++) acc[mi][nj][i] = 0.f;

    const int NC = K >> 5;
#pragma unroll
    for (int s = 0; s < 2; s++) {
        const int k0 = s << 5;
        uint32_t sa = sbase + s * STAGE_B;
        cp16(sa + faoff, gA + k0);
        cp16(sa + faoff + 16, gA + k0 + 8);
        cp16(sa + fboff, gB + k0);
        CP_COMMIT();
    }
    CP_WAIT1();
    __syncthreads();

    uint32_t afc[2][4], bfc[4][2];
    uint32_t afn[2][4], bfn[4][2];
    ld_frags(sbase, sbase + BOFF, 0, arow, acol, brow, bcol, afc, bfc);

    for (int c = 0; c < NC; c++) {
        const uint32_t sA = sbase + (c % 3) * STAGE_B;
        const uint32_t sB = sA + BOFF;

        ld_frags(sA, sB, 16, arow, acol, brow, bcol, afn, bfn);

        if (c + 2 < NC) {
            const int k0 = (c + 2) << 5;
            uint32_t sa = sbase + ((c + 2) % 3) * STAGE_B;
            cp16(sa + faoff, gA + k0);
            cp16(sa + faoff + 16, gA + k0 + 8);
            cp16(sa + fboff, gB + k0);
            CP_COMMIT();
        }

#pragma unroll
        for (int mi = 0; mi < 2; mi++)
#pragma unroll
            for (int nj = 0; nj < 4; nj++)
                mma_h16(acc[mi][nj], afc[mi], bfc[nj]);

        if (c + 1 < NC) {
            if (c + 2 < NC) CP_WAIT1(); else CP_WAIT0();
            __syncthreads();
            const uint32_t nA = sbase + ((c + 1) % 3) * STAGE_B;
            ld_frags(nA, nA + BOFF, 0, arow, acol, brow, bcol, afc, bfc);
        }

#pragma unroll
        for (int mi = 0; mi < 2; mi++)
#pragma unroll
            for (int nj = 0; nj < 4; nj++)
                mma_h16(acc[mi][nj], afn[mi], bfn[nj]);
    }

    // epilogue (optional t-major -> b-major row remap)
#pragma unroll
    for (int mi = 0; mi < 2; mi++) {
        int gr0 = rowbase + bm + wm * 32 + mi * 16 + g;
#pragma unroll
        for (int nj = 0; nj < 4; nj++) {
            int col = bn + wn * 32 + nj * 8 + tig * 2;
            float b0 = bias[col], b1 = bias[col + 1];
            if (gr0 < M) {
                int orow = remap ? ((gr0 & 63) * (CAPLEN - 1) + (gr0 >> 6)) : gr0;
                float2 v = make_float2(acc[mi][nj][0] + b0, acc[mi][nj][1] + b1);
                *(float2*)&C[(size_t)orow * N + col] = v;
            }
            if (gr0 + 8 < M) {
                int orow = remap ? (((gr0 + 8) & 63) * (CAPLEN - 1) + ((gr0 + 8) >> 6)) : gr0 + 8;
                float2 v = make_float2(acc[mi][nj][2] + b0, acc[mi][nj][3] + b1);
                *(float2*)&C[(size_t)orow * N + col] = v;
            }
        }
    }
}

// ---------------- persistent LSTM recurrence (splittable): 128 CTAs x 4 cols ----------------
#define RP 133
#define HSH_B (64 * GH * 2)
#define RED_B (64 * RP * 4)
#define LSTM_SMEM (HSH_B + RED_B + 16)
#define H_BYTES (BATCH * GH * 2)
#define NCTA 128

__global__ void __launch_bounds__(256, 1)
lstm_mma(const float* __restrict__ W_hh, int t0, int t1, int load_c, int save_c) {
    extern __shared__ char sm8[];
    __half* wsh = (__half*)(sm8 + HSH_B);
    float*  red = (float*)(sm8 + HSH_B);
    uint32_t sbase;
    asm("{ .reg .u64 t; cvta.to.shared.u64 t, %1; cvt.u32.u64 %0, t; }" : "=r"(sbase) : "l"(sm8));
    const uint32_t MB = sbase + HSH_B + RED_B;

    const int tid = threadIdx.x, lane = tid & 31, wid = tid >> 5;
    const int g = lane >> 2, tig = lane & 3;
    const int j0 = blockIdx.x * 4;
    const int kw = wid * 64;
    const int cb = tid >> 2, cl = tid & 3;
    const int rowoff = (lane & 7) | (((lane >> 3) & 1) << 3);
    const int acol = (lane >> 4) * 8;

#pragma unroll
    for (int i = 0; i < 32; i++) {
        int idx = tid + (i << 8);
        int r = idx >> 9, k = idx & 511;
        int wrow = ((r >> 2) << 9) + j0 + (r & 3);
        wsh[r * GH + k] = __float2half(W_hh[(size_t)wrow * HDIM + k]);
    }
    if (tid == 0) MBAR_INIT(MB, 1);
    __syncthreads();

    uint32_t breg[2][4][2];
#pragma unroll
    for (int nj = 0; nj < 2; nj++)
#pragma unroll
        for (int kk = 0; kk < 4; kk++) {
            const __half* p = &wsh[(nj * 8 + g) * GH + kw + kk * 16 + tig * 2];
            breg[nj][kk][0] = *(const uint32_t*)p;
            breg[nj][kk][1] = *(const uint32_t*)(p + 8);
        }
    __syncthreads();

    float c_reg = load_c ? g_cstate[cb * HDIM + j0 + cl] : 0.f;
    uint32_t mph = 0;
    for (int t = t0; t < t1; t++) {
        const float* Gt = &g_G[((size_t)t * BATCH + cb) * GDIM + j0 + cl];
        float gI = __ldg(Gt);
        float gF = __ldg(Gt + 512);
        float gG = __ldg(Gt + 1024);
        float gO = __ldg(Gt + 1536);

        if (tid == 0) {
            if (t > 0) {
                unsigned v;
                do {
                    asm volatile("ld.acquire.gpu.global.u32 %0, [%1];"
                                 : "=r"(v) : "l"(&g_cnt[t - 1]));
                    if (v >= (unsigned)NCTA) break;
                    __nanosleep(32);
                } while (1);
            }
            asm volatile("fence.proxy.async;" ::: "memory");
            asm volatile("mbarrier.arrive.expect_tx.shared.b64 _, [%0], %1;"
                         :: "r"(MB), "r"((uint32_t)H_BYTES) : "memory");
            bulk_ld(sbase, &g_hH[t & 1][0], H_BYTES, MB);
        }
        mbar_wait(MB, mph);
        mph ^= 1;

        float acc[4][2][4];
#pragma unroll
        for (int mi = 0; mi < 4; mi++)
#pragma unroll
            for (int nj = 0; nj < 2; nj++)
#pragma unroll
                for (int i = 0; i < 4; i++) acc[mi][nj][i] = 0.f;
#pragma unroll
        for (int mi = 0; mi < 4; mi++) {
#pragma unroll
            for (int kk = 0; kk < 4; kk++) {
                uint32_t a[4];
                LDSM4(a[0], a[1], a[2], a[3],
                      sbase + (uint32_t)((mi * 16 + rowoff) * GH + kw + kk * 16 + acol) * 2);
                mma_h16(acc[mi][0], a, breg[0][kk]);
                mma_h16(acc[mi][1], a, breg[1][kk]);
            }
        }
#pragma unroll
        for (int mi = 0; mi < 4; mi++)
#pragma unroll
            for (int nj = 0; nj < 2; nj++) {
                int m0 = mi * 16 + g, n0 = nj * 8 + tig * 2;
                float* rp = &red[m0 * RP + wid * 16 + n0];
                rp[0] = acc[mi][nj][0];
                rp[1] = acc[mi][nj][1];
                rp[8 * RP] = acc[mi][nj][2];
                rp[8 * RP + 1] = acc[mi][nj][3];
            }
        __syncthreads();

        float s0 = 0.f, s1 = 0.f, s2 = 0.f, s3 = 0.f;
#pragma unroll
        for (int w = 0; w < 8; w++) {
            const float* rp = &red[cb * RP + w * 16 + cl];
            s0 += rp[0]; s1 += rp[4]; s2 += rp[8]; s3 += rp[12];
        }
        float xi = gI + s0, xf = gF + s1, xg = gG + s2, xo = gO + s3;
        float cn = sigf(xf) * c_reg + sigf(xi) * tanhf(xg);
        float hn = sigf(xo) * tanhf(cn);
        c_reg = cn;
        __half hh = __float2half(hn);
        g_hH[(t + 1) & 1][cb * GH + j0 + cl] = hh;
        if (t >= MAXFRAME)
            g_dechT[((size_t)(t - MAXFRAME) * BATCH + cb) * HDIM + j0 + cl] = hh;
        __syncthreads();
        if (tid == 0)
            asm volatile("red.release.gpu.global.add.u32 [%0], 1;" :: "l"(&g_cnt[t]) : "memory");
    }
    if (save_c) g_cstate[cb * HDIM + j0 + cl] = c_reg;
}

// ---------------- launch ----------------
extern "C" void kernel_launch(void* const* d_in, const int* in_sizes, int n_in,
                              void* d_out, int out_size) {
    const float* feature   = (const float*)d_in[0];
    const int*   captions  = (const int*)d_in[1];
    const float* embedding = (const float*)d_in[2];
    const float* W_ih      = (const float*)d_in[3];
    const float* W_hh      = (const float*)d_in[4];
    const float* b_ih      = (const float*)d_in[5];
    const float* b_hh      = (const float*)d_in[6];
    const float* W_lin     = (const float*)d_in[7];
    const float* b_lin     = (const float*)d_in[8];
    float* out = (float*)d_out;

    cudaFuncSetAttribute(h16_gemm, cudaFuncAttributeMaxDynamicSharedMemorySize, GEMM_SMEM);
    cudaFuncSetAttribute(lstm_mma, cudaFuncAttributeMaxDynamicSharedMemorySize, LSTM_SMEM);

    void *pXe, *pXd, *pG, *pBias, *pWih, *pWlin, *pDech;
    cudaGetSymbolAddress(&pXe, g_XencH);
    cudaGetSymbolAddress(&pXd, g_XdecH);
    cudaGetSymbolAddress(&pG, g_G);
    cudaGetSymbolAddress(&pBias, g_bias);
    cudaGetSymbolAddress(&pWih, g_WihH);
    cudaGetSymbolAddress(&pWlin, g_WlinH);
    cudaGetSymbolAddress(&pDech, g_dechT);

    cudaStream_t s2;
    cudaStreamCreateWithFlags(&s2, cudaStreamNonBlocking);
    cudaEvent_t ev1, ev2;
    cudaEventCreateWithFlags(&ev1, cudaEventDisableTiming);
    cudaEventCreateWithFlags(&ev2, cudaEventDisableTiming);

    // serial front
    prep_kernel<<<64, 256>>>(b_ih, b_hh);
    build_encA<<<640, 256>>>(feature);
    conv_h<<<1024, 256>>>(W_ih, (__half*)pWih, GDIM * XDIM / 8);
    h16_gemm<<<dim3(GDIM / 64, ENCROWS / 128), 256, GEMM_SMEM>>>(
        (const __half*)pXe, HDIM, (const __half*)pWih + HDIM, XDIM,
        (const float*)pBias, (float*)pG, ENCROWS, GDIM, HDIM, 0, 0);
    build_decA<<<640, 256>>>(feature, captions, embedding);
    conv_h<<<8000, 256>>>(W_lin, (__half*)pWlin, VOCAB * HDIM / 8);
    h16_gemm<<<dim3(GDIM / 64, DECROWS / 128), 256, GEMM_SMEM>>>(
        (const __half*)pXd, XDIM, (const __half*)pWih, XDIM,
        (const float*)pBias, (float*)pG + (size_t)ENCROWS * GDIM, DECROWS, GDIM, XDIM, 0, 0);

    // recurrence part1: t = 0..49 (produces dech t' = 0..9)
    lstm_mma<<<NCTA, 256, LSTM_SMEM>>>(W_hh, 0, TSPLIT, 0, 1);
    cudaEventRecord(ev1, 0);

    // fork: proj half A (t' < 10) on s2
    cudaStreamWaitEvent(s2, ev1, 0);
    h16_gemm<<<dim3(VOCAB / 64, 5), 256, GEMM_SMEM, s2>>>(
        (const __half*)pDech, HDIM, (const __half*)pWlin, HDIM,
        b_lin, out, OUTROWS, VOCAB, HDIM, 1, 0);
    cudaEventRecord(ev2, s2);

    // main: recurrence part2 (t = 50..58), then proj half B (t' = 10..18)
    lstm_mma<<<NCTA, 256, LSTM_SMEM>>>(W_hh, TSPLIT, TSTEPS - 1, 1, 0);
    h16_gemm<<<dim3(VOCAB / 64, 5), 256, GEMM_SMEM>>>(
        (const __half*)pDech + (size_t)640 * HDIM, HDIM, (const __half*)pWlin, HDIM,
        b_lin, out, OUTROWS, VOCAB, HDIM, 1, 640);

    // join
    cudaStreamWaitEvent(0, ev2, 0);
}

// round 16
// speedup vs baseline: 1.1839x; 1.1839x over previous
#include <cuda_runtime.h>
#include <cuda_fp16.h>
#include <math.h>
#include <stdint.h>

#define BATCH 64
#define TSTEPS 60
#define MAXFRAME 40
#define CAPLEN 20
#define HDIM 512
#define XDIM 1024
#define GDIM 2048
#define VOCAB 32000
#define OUTROWS 1216
#define GH 520
#define ENCROWS (MAXFRAME * BATCH)           // 2560
#define DECROWS (CAPLEN * BATCH)             // 1280
#define TSPLIT 50

// ---------------- device scratch ----------------
__device__ __half g_XencH[ENCROWS * HDIM];
__device__ __half g_XdecH[DECROWS * XDIM];
__device__ float  g_G[TSTEPS * BATCH * GDIM];
__device__ float  g_bias[GDIM];
__device__ __half g_WihH[GDIM * XDIM];
__device__ __half g_WlinH[VOCAB * HDIM];
__device__ __half g_hH[2][BATCH * GH];
__device__ __half g_dechT[1280 * HDIM];      // t-major: row = t'*64 + b
__device__ float  g_cstate[BATCH * HDIM];
__device__ unsigned g_cnt[TSTEPS];

// ---------------- helpers ----------------
__device__ __forceinline__ uint32_t f2h2(float a, float b) {
    __half2 h = __floats2half2_rn(a, b);
    return *(uint32_t*)&h;
}
__device__ __forceinline__ void mma_h16(float* c, const uint32_t* a, const uint32_t* b) {
    asm volatile(
        "mma.sync.aligned.m16n8k16.row.col.f32.f16.f16.f32 "
        "{%0,%1,%2,%3}, {%4,%5,%6,%7}, {%8,%9}, {%0,%1,%2,%3};"
        : "+f"(c[0]), "+f"(c[1]), "+f"(c[2]), "+f"(c[3])
        : "r"(a[0]), "r"(a[1]), "r"(a[2]), "r"(a[3]), "r"(b[0]), "r"(b[1]));
}
__device__ __forceinline__ float sigf(float x) { return 1.f / (1.f + __expf(-x)); }
__device__ __forceinline__ void cp16(uint32_t d, const void* s) {
    asm volatile("cp.async.cg.shared.global [%0], [%1], 16;" :: "r"(d), "l"(s));
}
#define CP_COMMIT() asm volatile("cp.async.commit_group;" ::: "memory")
#define CP_WAIT1()  asm volatile("cp.async.wait_group 1;" ::: "memory")
#define CP_WAIT0()  asm volatile("cp.async.wait_group 0;" ::: "memory")
#define LDSM4(r0, r1, r2, r3, a) \
    asm volatile("ldmatrix.sync.aligned.m8n8.x4.shared.b16 {%0,%1,%2,%3}, [%4];" \
        : "=r"(r0), "=r"(r1), "=r"(r2), "=r"(r3) : "r"(a))
#define MBAR_INIT(mb, c) asm volatile("mbarrier.init.shared.b64 [%0], %1;" :: "r"(mb), "r"(c) : "memory")
__device__ __forceinline__ void mbar_wait(uint32_t mb, uint32_t parity) {
    asm volatile(
        "{\n\t.reg .pred P;\n\t"
        "LAB_W%=:\n\t"
        "mbarrier.try_wait.parity.acquire.cta.shared::cta.b64 P, [%0], %1, 0x989680;\n\t"
        "@P bra.uni LAB_D%=;\n\t"
        "bra.uni LAB_W%=;\n\t"
        "LAB_D%=:\n\t}" :: "r"(mb), "r"(parity) : "memory");
}
__device__ __forceinline__ void bulk_ld(uint32_t dst, const void* src, uint32_t bytes, uint32_t mb) {
    asm volatile(
        "cp.async.bulk.shared::cluster.global.mbarrier::complete_tx::bytes [%0], [%1], %2, [%3];"
        :: "r"(dst), "l"(src), "r"(bytes), "r"(mb) : "memory");
}

// ---------------- build enc A ----------------
__global__ void build_encA(const float* __restrict__ feature) {
    int idx = blockIdx.x * 256 + threadIdx.x;
    int r = idx >> 6, c8 = idx & 63;
    int t = r >> 6, b = r & 63;
    const float4* src = (const float4*)&feature[((size_t)b * TSTEPS + t) * HDIM + c8 * 8];
    float4 lo = src[0], hi = src[1];
    uint4 o;
    o.x = f2h2(lo.x, lo.y); o.y = f2h2(lo.z, lo.w);
    o.z = f2h2(hi.x, hi.y); o.w = f2h2(hi.z, hi.w);
    ((uint4*)g_XencH)[idx] = o;
}

// ---------------- build dec A ----------------
__global__ void build_decA(const float* __restrict__ feature,
                           const int* __restrict__ captions,
                           const float* __restrict__ embedding) {
    int idx = blockIdx.x * 256 + threadIdx.x;
    int r = idx >> 7, c8 = idx & 127;
    int tp = r >> 6, b = r & 63;
    float4 lo, hi;
    if (c8 < 64) {
        int cap = captions[b * CAPLEN + tp];
        const float4* src = (const float4*)&embedding[(size_t)cap * HDIM + c8 * 8];
        lo = src[0]; hi = src[1];
    } else {
        const float4* src = (const float4*)&feature[((size_t)b * TSTEPS + MAXFRAME + tp) * HDIM + (c8 - 64) * 8];
        lo = src[0]; hi = src[1];
    }
    uint4 o;
    o.x = f2h2(lo.x, lo.y); o.y = f2h2(lo.z, lo.w);
    o.z = f2h2(hi.x, hi.y); o.w = f2h2(hi.z, hi.w);
    ((uint4*)g_XdecH)[idx] = o;
}

// ---------------- fp32 -> fp16 convert ----------------
__global__ void conv_h(const float* __restrict__ s, __half* __restrict__ d, int n8) {
    int i = blockIdx.x * 256 + threadIdx.x;
    if (i < n8) {
        float4 a = ((const float4*)s)[i * 2];
        float4 b = ((const float4*)s)[i * 2 + 1];
        uint4 o;
        o.x = f2h2(a.x, a.y); o.y = f2h2(a.z, a.w);
        o.z = f2h2(b.x, b.y); o.w = f2h2(b.z, b.w);
        ((uint4*)d)[i] = o;
    }
}

// ---------------- prep ----------------
__global__ void prep_kernel(const float* __restrict__ b_ih, const float* __restrict__ b_hh) {
    int idx = blockIdx.x * 256 + threadIdx.x;
    ((uint32_t*)g_hH)[idx] = 0u;
    ((uint32_t*)g_hH)[idx + 16384] = 0u;
    if (idx < 512) ((uint32_t*)g_hH)[idx + 32768] = 0u;
    ((uint32_t*)g_dechT)[OUTROWS * HDIM / 2 + idx] = 0u;
    if (idx < GDIM) g_bias[idx] = b_ih[idx] + b_hh[idx];
    if (idx < TSTEPS) g_cnt[idx] = 0u;
}

// ---------------- fp16 mma GEMM (R14 champion: 128x128, cp.async 3-stage, sw-pipelined) ----------------
#define GP 40
#define STAGE_B (128 * GP * 2 * 2)
#define GEMM_SMEM (3 * STAGE_B)

__device__ __forceinline__ void ld_frags(uint32_t sA, uint32_t sB, int k0,
                                         int arow, int acol, int brow, int bcol,
                                         uint32_t af[2][4], uint32_t bf[8][2]) {
#pragma unroll
    for (int mi = 0; mi < 2; mi++)
        LDSM4(af[mi][0], af[mi][1], af[mi][2], af[mi][3],
              sA + (uint32_t)((arow + mi * 16) * GP + k0 + acol) * 2);
#pragma unroll
    for (int p = 0; p < 4; p++)
        LDSM4(bf[2 * p][0], bf[2 * p][1], bf[2 * p + 1][0], bf[2 * p + 1][1],
              sB + (uint32_t)((brow + p * 16) * GP + k0 + bcol) * 2);
}

__global__ void __launch_bounds__(256, 2)
h16_gemm(const __half* __restrict__ A, int lda,
         const __half* __restrict__ B, int ldb,
         const float* __restrict__ bias, float* __restrict__ C,
         int M, int N, int K, int remap, int rowbase) {
    extern __shared__ __half sh[];
    uint32_t sbase;
    asm("{ .reg .u64 t; cvta.to.shared.u64 t, %1; cvt.u32.u64 %0, t; }" : "=r"(sbase) : "l"(sh));

    const int tid = threadIdx.x, lane = tid & 31, wid = tid >> 5;
    const int wm = wid & 3, wn = wid >> 2;
    const int g = lane >> 2, tig = lane & 3;
    const int bm = blockIdx.y * 128, bn = blockIdx.x * 128;

    const int frow = tid >> 1, fho = (tid & 1) * 16;
    const __half* gA = &A[(size_t)(bm + frow) * lda + fho];
    const __half* gB = &B[(size_t)(bn + frow) * ldb + fho];
    const uint32_t fsoff = (uint32_t)(frow * GP + fho) * 2;

    const int arow = wm * 32 + ((lane & 7) | (((lane >> 3) & 1) << 3));
    const int acol = (lane >> 4) * 8;
    const int brow = wn * 64 + (lane & 7) + ((lane >> 4) << 3);
    const int bcol = ((lane >> 3) & 1) * 8;

    float acc[2][8][4];
#pragma unroll
    for (int mi = 0; mi < 2; mi++)
#pragma unroll
        for (int nj = 0; nj < 8; nj++)
#pragma unroll
            for (int i = 0; i < 4; i++) acc[mi][nj][i] = 0.f;

    const int NC = K >> 5;
#pragma unroll
    for (int s = 0; s < 2; s++) {
        uint32_t sa = sbase + s * STAGE_B + fsoff;
        uint32_t sb = sa + 128 * GP * 2;
        const __half* pa = gA + (s << 5);
        const __half* pb = gB + (s << 5);
        cp16(sa, pa); cp16(sa + 16, pa + 8);
        cp16(sb, pb); cp16(sb + 16, pb + 8);
        CP_COMMIT();
    }
    CP_WAIT1();
    __syncthreads();

    uint32_t afc[2][4], bfc[8][2];
    uint32_t afn[2][4], bfn[8][2];
    ld_frags(sbase, sbase + 128 * GP * 2, 0, arow, acol, brow, bcol, afc, bfc);

    for (int c = 0; c < NC; c++) {
        const uint32_t sA = sbase + (c % 3) * STAGE_B;
        const uint32_t sB = sA + 128 * GP * 2;

        ld_frags(sA, sB, 16, arow, acol, brow, bcol, afn, bfn);

        if (c + 2 < NC) {
            const int ns = (c + 2) % 3;
            uint32_t sa = sbase + ns * STAGE_B + fsoff;
            uint32_t sb = sa + 128 * GP * 2;
            const __half* pa = gA + ((c + 2) << 5);
            const __half* pb = gB + ((c + 2) << 5);
            cp16(sa, pa); cp16(sa + 16, pa + 8);
            cp16(sb, pb); cp16(sb + 16, pb + 8);
            CP_COMMIT();
        }

#pragma unroll
        for (int mi = 0; mi < 2; mi++)
#pragma unroll
            for (int nj = 0; nj < 8; nj++)
                mma_h16(acc[mi][nj], afc[mi], bfc[nj]);

        if (c + 1 < NC) {
            if (c + 2 < NC) CP_WAIT1(); else CP_WAIT0();
            __syncthreads();
            const uint32_t nA = sbase + ((c + 1) % 3) * STAGE_B;
            ld_frags(nA, nA + 128 * GP * 2, 0, arow, acol, brow, bcol, afc, bfc);
        }

#pragma unroll
        for (int mi = 0; mi < 2; mi++)
#pragma unroll
            for (int nj = 0; nj < 8; nj++)
                mma_h16(acc[mi][nj], afn[mi], bfn[nj]);
    }

    // epilogue (optional t-major -> b-major row remap)
#pragma unroll
    for (int mi = 0; mi < 2; mi++) {
        int gr0 = rowbase + bm + wm * 32 + mi * 16 + g;
#pragma unroll
        for (int nj = 0; nj < 8; nj++) {
            int col = bn + wn * 64 + nj * 8 + tig * 2;
            float b0 = bias[col], b1 = bias[col + 1];
            if (gr0 < M) {
                int orow = remap ? ((gr0 & 63) * (CAPLEN - 1) + (gr0 >> 6)) : gr0;
                float2 v = make_float2(acc[mi][nj][0] + b0, acc[mi][nj][1] + b1);
                *(float2*)&C[(size_t)orow * N + col] = v;
            }
            if (gr0 + 8 < M) {
                int orow = remap ? (((gr0 + 8) & 63) * (CAPLEN - 1) + ((gr0 + 8) >> 6)) : gr0 + 8;
                float2 v = make_float2(acc[mi][nj][2] + b0, acc[mi][nj][3] + b1);
                *(float2*)&C[(size_t)orow * N + col] = v;
            }
        }
    }
}

// ---------------- persistent LSTM recurrence (splittable): 128 CTAs x 4 cols ----------------
#define RP 133
#define HSH_B (64 * GH * 2)
#define RED_B (64 * RP * 4)
#define LSTM_SMEM (HSH_B + RED_B + 16)
#define H_BYTES (BATCH * GH * 2)
#define NCTA 128

__global__ void __launch_bounds__(256, 1)
lstm_mma(const float* __restrict__ W_hh, int t0, int t1, int load_c, int save_c) {
    extern __shared__ char sm8[];
    __half* wsh = (__half*)(sm8 + HSH_B);    // init-only, overlaid by red
    float*  red = (float*)(sm8 + HSH_B);
    uint32_t sbase;
    asm("{ .reg .u64 t; cvta.to.shared.u64 t, %1; cvt.u32.u64 %0, t; }" : "=r"(sbase) : "l"(sm8));
    const uint32_t MB = sbase + HSH_B + RED_B;

    const int tid = threadIdx.x, lane = tid & 31, wid = tid >> 5;
    const int g = lane >> 2, tig = lane & 3;
    const int j0 = blockIdx.x * 4;
    const int kw = wid * 64;
    const int cb = tid >> 2, cl = tid & 3;
    const int rowoff = (lane & 7) | (((lane >> 3) & 1) << 3);
    const int acol = (lane >> 4) * 8;

#pragma unroll
    for (int i = 0; i < 32; i++) {
        int idx = tid + (i << 8);
        int r = idx >> 9, k = idx & 511;
        int wrow = ((r >> 2) << 9) + j0 + (r & 3);
        wsh[r * GH + k] = __float2half(W_hh[(size_t)wrow * HDIM + k]);
    }
    if (tid == 0) MBAR_INIT(MB, 1);
    __syncthreads();

    uint32_t breg[2][4][2];
#pragma unroll
    for (int nj = 0; nj < 2; nj++)
#pragma unroll
        for (int kk = 0; kk < 4; kk++) {
            const __half* p = &wsh[(nj * 8 + g) * GH + kw + kk * 16 + tig * 2];
            breg[nj][kk][0] = *(const uint32_t*)p;
            breg[nj][kk][1] = *(const uint32_t*)(p + 8);
        }
    __syncthreads();

    float c_reg = load_c ? g_cstate[cb * HDIM + j0 + cl] : 0.f;
    uint32_t mph = 0;
    for (int t = t0; t < t1; t++) {
        const float* Gt = &g_G[((size_t)t * BATCH + cb) * GDIM + j0 + cl];
        float gI = __ldg(Gt);
        float gF = __ldg(Gt + 512);
        float gG = __ldg(Gt + 1024);
        float gO = __ldg(Gt + 1536);

        if (tid == 0) {
            if (t > 0) {
                unsigned v;
                do {
                    asm volatile("ld.acquire.gpu.global.u32 %0, [%1];"
                                 : "=r"(v) : "l"(&g_cnt[t - 1]));
                    if (v >= (unsigned)NCTA) break;
                    __nanosleep(32);
                } while (1);
            }
            asm volatile("fence.proxy.async;" ::: "memory");
            asm volatile("mbarrier.arrive.expect_tx.shared.b64 _, [%0], %1;"
                         :: "r"(MB), "r"((uint32_t)H_BYTES) : "memory");
            bulk_ld(sbase, &g_hH[t & 1][0], H_BYTES, MB);
        }
        mbar_wait(MB, mph);
        mph ^= 1;

        float acc[4][2][4];
#pragma unroll
        for (int mi = 0; mi < 4; mi++)
#pragma unroll
            for (int nj = 0; nj < 2; nj++)
#pragma unroll
                for (int i = 0; i < 4; i++) acc[mi][nj][i] = 0.f;
#pragma unroll
        for (int mi = 0; mi < 4; mi++) {
#pragma unroll
            for (int kk = 0; kk < 4; kk++) {
                uint32_t a[4];
                LDSM4(a[0], a[1], a[2], a[3],
                      sbase + (uint32_t)((mi * 16 + rowoff) * GH + kw + kk * 16 + acol) * 2);
                mma_h16(acc[mi][0], a, breg[0][kk]);
                mma_h16(acc[mi][1], a, breg[1][kk]);
            }
        }
#pragma unroll
        for (int mi = 0; mi < 4; mi++)
#pragma unroll
            for (int nj = 0; nj < 2; nj++) {
                int m0 = mi * 16 + g, n0 = nj * 8 + tig * 2;
                float* rp = &red[m0 * RP + wid * 16 + n0];
                rp[0] = acc[mi][nj][0];
                rp[1] = acc[mi][nj][1];
                rp[8 * RP] = acc[mi][nj][2];
                rp[8 * RP + 1] = acc[mi][nj][3];
            }
        __syncthreads();

        float s0 = 0.f, s1 = 0.f, s2 = 0.f, s3 = 0.f;
#pragma unroll
        for (int w = 0; w < 8; w++) {
            const float* rp = &red[cb * RP + w * 16 + cl];
            s0 += rp[0]; s1 += rp[4]; s2 += rp[8]; s3 += rp[12];
        }
        float xi = gI + s0, xf = gF + s1, xg = gG + s2, xo = gO + s3;
        float cn = sigf(xf) * c_reg + sigf(xi) * tanhf(xg);
        float hn = sigf(xo) * tanhf(cn);
        c_reg = cn;
        __half hh = __float2half(hn);
        g_hH[(t + 1) & 1][cb * GH + j0 + cl] = hh;
        if (t >= MAXFRAME)
            g_dechT[((size_t)(t - MAXFRAME) * BATCH + cb) * HDIM + j0 + cl] = hh;
        __syncthreads();
        if (tid == 0)
            asm volatile("red.release.gpu.global.add.u32 [%0], 1;" :: "l"(&g_cnt[t]) : "memory");
    }
    if (save_c) g_cstate[cb * HDIM + j0 + cl] = c_reg;
}

// ---------------- launch ----------------
extern "C" void kernel_launch(void* const* d_in, const int* in_sizes, int n_in,
                              void* d_out, int out_size) {
    const float* feature   = (const float*)d_in[0];
    const int*   captions  = (const int*)d_in[1];
    const float* embedding = (const float*)d_in[2];
    const float* W_ih      = (const float*)d_in[3];
    const float* W_hh      = (const float*)d_in[4];
    const float* b_ih      = (const float*)d_in[5];
    const float* b_hh      = (const float*)d_in[6];
    const float* W_lin     = (const float*)d_in[7];
    const float* b_lin     = (const float*)d_in[8];
    float* out = (float*)d_out;

    cudaFuncSetAttribute(h16_gemm, cudaFuncAttributeMaxDynamicSharedMemorySize, GEMM_SMEM);
    cudaFuncSetAttribute(lstm_mma, cudaFuncAttributeMaxDynamicSharedMemorySize, LSTM_SMEM);

    void *pXe, *pXd, *pG, *pBias, *pWih, *pWlin, *pDech;
    cudaGetSymbolAddress(&pXe, g_XencH);
    cudaGetSymbolAddress(&pXd, g_XdecH);
    cudaGetSymbolAddress(&pG, g_G);
    cudaGetSymbolAddress(&pBias, g_bias);
    cudaGetSymbolAddress(&pWih, g_WihH);
    cudaGetSymbolAddress(&pWlin, g_WlinH);
    cudaGetSymbolAddress(&pDech, g_dechT);

    cudaStream_t s2;
    cudaStreamCreateWithFlags(&s2, cudaStreamNonBlocking);
    cudaEvent_t ev0, evA, evD, ev1, ev2;
    cudaEventCreateWithFlags(&ev0, cudaEventDisableTiming);
    cudaEventCreateWithFlags(&evA, cudaEventDisableTiming);
    cudaEventCreateWithFlags(&evD, cudaEventDisableTiming);
    cudaEventCreateWithFlags(&ev1, cudaEventDisableTiming);
    cudaEventCreateWithFlags(&ev2, cudaEventDisableTiming);

    // main: prep + enc chain
    prep_kernel<<<64, 256>>>(b_ih, b_hh);
    cudaEventRecord(ev0, 0);                 // fork point for s2

    // s2: fully independent work, overlaps the enc chain
    cudaStreamWaitEvent(s2, ev0, 0);
    conv_h<<<8000, 256, 0, s2>>>(W_lin, (__half*)pWlin, VOCAB * HDIM / 8);
    build_decA<<<640, 256, 0, s2>>>(feature, captions, embedding);

    // main: enc chain
    build_encA<<<640, 256>>>(feature);
    conv_h<<<1024, 256>>>(W_ih, (__half*)pWih, GDIM * XDIM / 8);
    cudaEventRecord(evA, 0);                 // bias + WihH ready

    // s2: dec GEMM (needs XdecH + WihH + bias) — overlaps enc GEMM on main
    cudaStreamWaitEvent(s2, evA, 0);
    h16_gemm<<<dim3(GDIM / 128, DECROWS / 128), 256, GEMM_SMEM, s2>>>(
        (const __half*)pXd, XDIM, (const __half*)pWih, XDIM,
        (const float*)pBias, (float*)pG + (size_t)ENCROWS * GDIM, DECROWS, GDIM, XDIM, 0, 0);
    cudaEventRecord(evD, s2);

    // main: enc GEMM
    h16_gemm<<<dim3(GDIM / 128, ENCROWS / 128), 256, GEMM_SMEM>>>(
        (const __half*)pXe, HDIM, (const __half*)pWih + HDIM, XDIM,
        (const float*)pBias, (float*)pG, ENCROWS, GDIM, HDIM, 0, 0);

    // join dec gates before recurrence part1 (covers t = 40..49)
    cudaStreamWaitEvent(0, evD, 0);
    lstm_mma<<<NCTA, 256, LSTM_SMEM>>>(W_hh, 0, TSPLIT, 0, 1);
    cudaEventRecord(ev1, 0);

    // s2: proj half A (t' < 10) overlaps recurrence part2
    cudaStreamWaitEvent(s2, ev1, 0);
    h16_gemm<<<dim3(VOCAB / 128, 5), 256, GEMM_SMEM, s2>>>(
        (const __half*)pDech, HDIM, (const __half*)pWlin, HDIM,
        b_lin, out, OUTROWS, VOCAB, HDIM, 1, 0);
    cudaEventRecord(ev2, s2);

    // main: recurrence part2, then proj half B
    lstm_mma<<<NCTA, 256, LSTM_SMEM>>>(W_hh, TSPLIT, TSTEPS - 1, 1, 0);
    h16_gemm<<<dim3(VOCAB / 128, 5), 256, GEMM_SMEM>>>(
        (const __half*)pDech + (size_t)640 * HDIM, HDIM, (const __half*)pWlin, HDIM,
        b_lin, out, OUTROWS, VOCAB, HDIM, 1, 640);

    // join
    cudaStreamWaitEvent(0, ev2, 0);
}